// round 1
// baseline (speedup 1.0000x reference)
#include <cuda_runtime.h>
#include <math.h>

#define SB 32
#define SH 2048
#define ST 39
#define SV 8000
#define SE 50

typedef unsigned long long u64;

__device__ __forceinline__ u64 pk2(float lo, float hi){
    u64 r; asm("mov.b64 %0, {%1,%2};" : "=l"(r) : "f"(lo), "f"(hi)); return r;
}
__device__ __forceinline__ u64 ffma2(u64 a, u64 b, u64 c){
    u64 d; asm("fma.rn.f32x2 %0, %1, %2, %3;" : "=l"(d) : "l"(a), "l"(b), "l"(c)); return d;
}
__device__ __forceinline__ float red2(u64 a){
    float lo, hi; asm("mov.b64 {%0,%1}, %2;" : "=f"(lo), "=f"(hi) : "l"(a)); return lo + hi;
}
__device__ __forceinline__ float sigf(float x){ return 1.0f/(1.0f + expf(-x)); }

// ---- scratch (device globals; no allocation allowed) ----
// State layout: float4 groups along k: idx(k,b) = ((k>>2)*32 + b)*4 + (k&3)
__device__ __align__(16) float d_Xg[(size_t)ST*8192*SB];     // precomputed x@Wih^T + bih + bhh, [t][j][b]
__device__ __align__(16) float d_h[2][SH*SB];                // LSTM h, double buffered
__device__ __align__(16) float d_c[SH*SB];                   // LSTM c
__device__ __align__(16) float d_hg[2][SH*SB];               // GRU h, double buffered
__device__ __align__(16) float d_gh[6144*SB];                // gh = hg@gWhh^T + gbhh, [j][b]
__device__ __align__(16) float d_hgAll[(size_t)ST*SH*SB];    // all GRU states for final GEMM

// ---- init: carry = (features, features, features), transpose to k-major float4 layout ----
__global__ void setup_kernel(const float* __restrict__ feat){
    int i = blockIdx.x*blockDim.x + threadIdx.x;   // 0..65535
    int b = i >> 11, k = i & 2047;
    float v = feat[b*SH + k];
    int d = ((k>>2)*SB + b)*4 + (k&3);
    d_h[0][d] = v; d_c[d] = v; d_hg[0][d] = v;
}

// ---- precompute Xg[t][j][b] = emb[cap[b][t]] . Wih[j] + bih[j] + bhh[j] ----
__global__ void xg_kernel(const int* __restrict__ captions, const float* __restrict__ emb,
                          const float* __restrict__ Wih, const float* __restrict__ bih,
                          const float* __restrict__ bhh){
    __shared__ float embS[SE*SB];    // [e][b]
    int t = blockIdx.x;              // 0..38
    int jc = blockIdx.y;             // 0..7
    int tid = threadIdx.x;
    for (int i = tid; i < SB*SE; i += 256){
        int b = i / SE, e = i % SE;
        int cap = captions[b*40 + t];
        embS[e*SB + b] = emb[(size_t)cap*SE + e];
    }
    __syncthreads();
    int lane = tid & 31, wid = tid >> 5;
    for (int j = jc*1024 + wid; j < jc*1024 + 1024; j += 8){
        float acc = bih[j] + bhh[j];
        const float* wr = Wih + (size_t)j*SE;
        #pragma unroll
        for (int e = 0; e < SE; e++) acc = fmaf(wr[e], embS[e*SB + lane], acc);
        d_Xg[((size_t)t*8192 + j)*SB + lane] = acc;
    }
}

// ---- step phase A: LSTM gates (h@Whh^T) + elementwise; GRU hidden term (hg@gWhh^T) ----
// tasks: 512 LSTM quads (4 cols x 4 gates = 16 dots) + 768 GH octets (8 dots). grid 160x256.
__global__ void stepA_kernel(const float* __restrict__ Whh, const float* __restrict__ gWhh,
                             const float* __restrict__ gbhh, int t){
    int rp = t & 1, wp = rp ^ 1;
    int task = blockIdx.x*8 + (threadIdx.x >> 5);
    int lane = threadIdx.x & 31;
    if (task < 512){
        int j0 = task*4;
        const float4* xq = (const float4*)(d_h[rp]);
        u64 acc[16];
        #pragma unroll
        for (int i = 0; i < 16; i++) acc[i] = 0ull;
        #pragma unroll 1
        for (int q = 0; q < 512; q++){
            float4 hv = xq[q*SB + lane];
            u64 hlo = pk2(hv.x, hv.y), hhi = pk2(hv.z, hv.w);
            #pragma unroll
            for (int g = 0; g < 4; g++){
                #pragma unroll
                for (int c = 0; c < 4; c++){
                    const float4 wv = *(const float4*)(Whh + (size_t)(g*2048 + j0 + c)*SH + 4*q);
                    int a = g*4 + c;
                    acc[a] = ffma2(pk2(wv.x, wv.y), hlo, acc[a]);
                    acc[a] = ffma2(pk2(wv.z, wv.w), hhi, acc[a]);
                }
            }
        }
        size_t xb = (size_t)t*8192*SB;
        #pragma unroll
        for (int c = 0; c < 4; c++){
            int j = j0 + c;
            float gi = red2(acc[0*4+c]) + d_Xg[xb + (size_t)(j       )*SB + lane];
            float gf = red2(acc[1*4+c]) + d_Xg[xb + (size_t)(j + 2048)*SB + lane];
            float gg = red2(acc[2*4+c]) + d_Xg[xb + (size_t)(j + 4096)*SB + lane];
            float go = red2(acc[3*4+c]) + d_Xg[xb + (size_t)(j + 6144)*SB + lane];
            int ci = ((j>>2)*SB + lane)*4 + (j&3);
            float cold = d_c[ci];
            float cn = sigf(gf)*cold + sigf(gi)*tanhf(gg);
            d_c[ci] = cn;
            d_h[wp][ci] = sigf(go)*tanhf(cn);
        }
    } else {
        int j0 = (task - 512)*8;
        const float4* xq = (const float4*)(d_hg[rp]);
        u64 acc[8];
        #pragma unroll
        for (int i = 0; i < 8; i++) acc[i] = 0ull;
        #pragma unroll 1
        for (int q = 0; q < 512; q++){
            float4 hv = xq[q*SB + lane];
            u64 hlo = pk2(hv.x, hv.y), hhi = pk2(hv.z, hv.w);
            #pragma unroll
            for (int r = 0; r < 8; r++){
                const float4 wv = *(const float4*)(gWhh + (size_t)(j0 + r)*SH + 4*q);
                acc[r] = ffma2(pk2(wv.x, wv.y), hlo, acc[r]);
                acc[r] = ffma2(pk2(wv.z, wv.w), hhi, acc[r]);
            }
        }
        #pragma unroll
        for (int r = 0; r < 8; r++)
            d_gh[(size_t)(j0 + r)*SB + lane] = red2(acc[r]) + gbhh[j0 + r];
    }
}

// ---- step phase B: gi = c@gWih^T + gbih; GRU elementwise -> hg ----
// 512 tasks (4 cols x 3 gates = 12 dots). grid 64x256.
__global__ void stepB_kernel(const float* __restrict__ gWih, const float* __restrict__ gbih, int t){
    int rp = t & 1, wp = rp ^ 1;
    int task = blockIdx.x*8 + (threadIdx.x >> 5);
    int lane = threadIdx.x & 31;
    int j0 = task*4;
    const float4* xq = (const float4*)(d_c);
    u64 acc[12];
    #pragma unroll
    for (int i = 0; i < 12; i++) acc[i] = 0ull;
    #pragma unroll 1
    for (int q = 0; q < 512; q++){
        float4 hv = xq[q*SB + lane];
        u64 hlo = pk2(hv.x, hv.y), hhi = pk2(hv.z, hv.w);
        #pragma unroll
        for (int s = 0; s < 3; s++){
            #pragma unroll
            for (int c = 0; c < 4; c++){
                const float4 wv = *(const float4*)(gWih + (size_t)(s*2048 + j0 + c)*SH + 4*q);
                int a = s*4 + c;
                acc[a] = ffma2(pk2(wv.x, wv.y), hlo, acc[a]);
                acc[a] = ffma2(pk2(wv.z, wv.w), hhi, acc[a]);
            }
        }
    }
    #pragma unroll
    for (int c = 0; c < 4; c++){
        int j = j0 + c;
        float r_ = sigf(red2(acc[0*4+c]) + gbih[j       ] + d_gh[(size_t)(j       )*SB + lane]);
        float z_ = sigf(red2(acc[1*4+c]) + gbih[j + 2048] + d_gh[(size_t)(j + 2048)*SB + lane]);
        float n_ = tanhf(red2(acc[2*4+c]) + gbih[j + 4096] + r_*d_gh[(size_t)(j + 4096)*SB + lane]);
        int ci = ((j>>2)*SB + lane)*4 + (j&3);
        float hgo = d_hg[rp][ci];
        float hg = (1.0f - z_)*n_ + z_*hgo;
        d_hg[wp][ci] = hg;
        d_hgAll[(size_t)t*(SH*SB) + ci] = hg;
    }
}

// ---- final projection: out[b][t][v] = hgAll[t][.][b] . linW[v] + linb[v] ----
// warp task: 3 timesteps x 8 vocab cols; 13 t-groups x 1000 col-groups = 13000 warps; grid 1625x256.
__global__ void final_kernel(const float* __restrict__ linW, const float* __restrict__ linb,
                             float* __restrict__ out){
    int w = blockIdx.x*8 + (threadIdx.x >> 5);
    int lane = threadIdx.x & 31;
    int tg = w / 1000, cg = w % 1000;
    int t0 = tg*3, v0 = cg*8;
    const float4* xq0 = (const float4*)(d_hgAll + (size_t)(t0    )*(SH*SB));
    const float4* xq1 = (const float4*)(d_hgAll + (size_t)(t0 + 1)*(SH*SB));
    const float4* xq2 = (const float4*)(d_hgAll + (size_t)(t0 + 2)*(SH*SB));
    u64 acc[24];
    #pragma unroll
    for (int i = 0; i < 24; i++) acc[i] = 0ull;
    #pragma unroll 1
    for (int q = 0; q < 512; q++){
        float4 h0 = xq0[q*SB + lane];
        float4 h1 = xq1[q*SB + lane];
        float4 h2 = xq2[q*SB + lane];
        u64 l0 = pk2(h0.x, h0.y), m0 = pk2(h0.z, h0.w);
        u64 l1 = pk2(h1.x, h1.y), m1 = pk2(h1.z, h1.w);
        u64 l2 = pk2(h2.x, h2.y), m2 = pk2(h2.z, h2.w);
        #pragma unroll
        for (int c = 0; c < 8; c++){
            const float4 wv = *(const float4*)(linW + (size_t)(v0 + c)*SH + 4*q);
            u64 wl = pk2(wv.x, wv.y), wh = pk2(wv.z, wv.w);
            acc[0*8+c] = ffma2(wl, l0, acc[0*8+c]); acc[0*8+c] = ffma2(wh, m0, acc[0*8+c]);
            acc[1*8+c] = ffma2(wl, l1, acc[1*8+c]); acc[1*8+c] = ffma2(wh, m1, acc[1*8+c]);
            acc[2*8+c] = ffma2(wl, l2, acc[2*8+c]); acc[2*8+c] = ffma2(wh, m2, acc[2*8+c]);
        }
    }
    #pragma unroll
    for (int tt = 0; tt < 3; tt++){
        #pragma unroll
        for (int c = 0; c < 8; c++){
            out[(size_t)lane*(ST*SV) + (size_t)(t0 + tt)*SV + (v0 + c)]
                = red2(acc[tt*8 + c]) + linb[v0 + c];
        }
    }
}

extern "C" void kernel_launch(void* const* d_in, const int* in_sizes, int n_in,
                              void* d_out, int out_size){
    const float* features = (const float*)d_in[0];
    const int*   captions = (const int*)  d_in[1];
    const float* emb      = (const float*)d_in[2];
    const float* lWih     = (const float*)d_in[3];
    const float* lbih     = (const float*)d_in[4];
    const float* lWhh     = (const float*)d_in[5];
    const float* lbhh     = (const float*)d_in[6];
    const float* gWih     = (const float*)d_in[7];
    const float* gbih     = (const float*)d_in[8];
    const float* gWhh     = (const float*)d_in[9];
    const float* gbhh     = (const float*)d_in[10];
    const float* linW     = (const float*)d_in[11];
    const float* linb     = (const float*)d_in[12];
    float* out = (float*)d_out;

    setup_kernel<<<256, 256>>>(features);
    xg_kernel<<<dim3(ST, 8), 256>>>(captions, emb, lWih, lbih, lbhh);
    for (int t = 0; t < ST; t++){
        stepA_kernel<<<160, 256>>>(lWhh, gWhh, gbhh, t);
        stepB_kernel<<<64, 256>>>(gWih, gbih, t);
    }
    final_kernel<<<1625, 256>>>(linW, linb, out);
}

// round 4
// speedup vs baseline: 7.2834x; 7.2834x over previous
#include <cuda_runtime.h>
#include <math.h>

#define SB 32
#define SH 2048
#define ST 39
#define SV 8000
#define SE 50
#define NKQ 512      // K in float4 units
#define CHQ 16       // float4-k per chunk (64 floats)
#define NCH 32       // chunks

typedef unsigned long long u64;

__device__ __forceinline__ u64 pk2(float lo, float hi){
    u64 r; asm("mov.b64 %0, {%1,%2};" : "=l"(r) : "f"(lo), "f"(hi)); return r;
}
__device__ __forceinline__ u64 ffma2(u64 a, u64 b, u64 c){
    u64 d; asm("fma.rn.f32x2 %0, %1, %2, %3;" : "=l"(d) : "l"(a), "l"(b), "l"(c)); return d;
}
__device__ __forceinline__ float red2(u64 a){
    float lo, hi; asm("mov.b64 {%0,%1}, %2;" : "=f"(lo), "=f"(hi) : "l"(a)); return lo + hi;
}
__device__ __forceinline__ float sigf(float x){ return 1.0f/(1.0f + expf(-x)); }

// ---- scratch (device globals) ----
// State layout: float4 groups along k: f4 index (kq*32 + b), kq = k>>2
__device__ __align__(16) float d_Xg[(size_t)ST*8192*SB];
__device__ __align__(16) float d_h[2][SH*SB];
__device__ __align__(16) float d_c[SH*SB];
__device__ __align__(16) float d_hg[2][SH*SB];
__device__ __align__(16) float d_gh[6144*SB];
__device__ __align__(16) float d_hgAll[(size_t)ST*SH*SB];

__global__ void setup_kernel(const float* __restrict__ feat){
    int i = blockIdx.x*blockDim.x + threadIdx.x;
    int b = i >> 11, k = i & 2047;
    float v = feat[b*SH + k];
    int d = ((k>>2)*SB + b)*4 + (k&3);
    d_h[0][d] = v; d_c[d] = v; d_hg[0][d] = v;
}

__global__ void xg_kernel(const int* __restrict__ captions, const float* __restrict__ emb,
                          const float* __restrict__ Wih, const float* __restrict__ bih,
                          const float* __restrict__ bhh){
    __shared__ float embS[SE*SB];
    int t = blockIdx.x, jc = blockIdx.y, tid = threadIdx.x;
    for (int i = tid; i < SB*SE; i += 256){
        int b = i / SE, e = i % SE;
        int cap = captions[b*40 + t];
        embS[e*SB + b] = emb[(size_t)cap*SE + e];
    }
    __syncthreads();
    int lane = tid & 31, wid = tid >> 5;
    for (int j = jc*1024 + wid; j < jc*1024 + 1024; j += 8){
        float acc = bih[j] + bhh[j];
        const float* wr = Wih + (size_t)j*SE;
        #pragma unroll
        for (int e = 0; e < SE; e++) acc = fmaf(wr[e], embS[e*SB + lane], acc);
        d_Xg[((size_t)t*8192 + j)*SB + lane] = acc;
    }
}

// ---- stepA: LSTM gates (h@Whh^T, 256 blocks) + GRU hidden term (hg@gWhh^T, 192 blocks) ----
__global__ void __launch_bounds__(256, 3) stepA_kernel(
        const float4* __restrict__ Whh4, const float4* __restrict__ gWhh4,
        const float* __restrict__ gbhh, int t){
    __shared__ float4 wbuf[2][512];   // 32 rows x 16 f4
    __shared__ float4 sbuf[2][512];   // 16 kq x 32 b
    int rp = t & 1, wp = rp ^ 1;
    int tid = threadIdx.x, lane = tid & 31, w = tid >> 5;
    bool isL = blockIdx.x < 256;
    const float4* W4; const float4* S4;
    int r0 = tid >> 4, kc0 = tid & 15;
    int r1 = r0 + 16;
    int rowg0, rowg1;
    int j0 = 0, rb = 0;
    if (isL){
        j0 = blockIdx.x * 8;
        W4 = Whh4; S4 = (const float4*)(d_h[rp]);
        rowg0 = (r0>>3)*2048 + j0 + (r0&7);
        rowg1 = (r1>>3)*2048 + j0 + (r1&7);
    } else {
        rb = (blockIdx.x - 256)*32;
        W4 = gWhh4; S4 = (const float4*)(d_hg[rp]);
        rowg0 = rb + r0;
        rowg1 = rb + r1;
    }
    const float4* wg0 = W4 + (size_t)rowg0*NKQ + kc0;
    const float4* wg1 = W4 + (size_t)rowg1*NKQ + kc0;
    int wOff[4];
    #pragma unroll
    for (int g = 0; g < 4; g++) wOff[g] = isL ? ((g*8 + w)*16) : ((w*4 + g)*16);

    // prologue: stage chunk 0
    float4 wr0 = wg0[0], wr1 = wg1[0];
    float4 sr0 = S4[tid], sr1 = S4[tid + 256];
    wbuf[0][tid] = wr0; wbuf[0][tid+256] = wr1;
    sbuf[0][tid] = sr0; sbuf[0][tid+256] = sr1;
    __syncthreads();

    u64 acc[4] = {0ull,0ull,0ull,0ull};
    #pragma unroll 1
    for (int ck = 0; ck < NCH; ck++){
        int cur = ck & 1;
        if (ck < NCH-1){
            wr0 = wg0[(ck+1)*CHQ]; wr1 = wg1[(ck+1)*CHQ];
            sr0 = S4[(ck+1)*512 + tid]; sr1 = S4[(ck+1)*512 + tid + 256];
        }
        #pragma unroll
        for (int kq = 0; kq < CHQ; kq++){
            float4 sv = sbuf[cur][kq*32 + lane];
            u64 slo = pk2(sv.x, sv.y), shi = pk2(sv.z, sv.w);
            #pragma unroll
            for (int g = 0; g < 4; g++){
                float4 wv = wbuf[cur][wOff[g] + kq];
                acc[g] = ffma2(pk2(wv.x,wv.y), slo, acc[g]);
                acc[g] = ffma2(pk2(wv.z,wv.w), shi, acc[g]);
            }
        }
        if (ck < NCH-1){
            int nxt = cur ^ 1;
            wbuf[nxt][tid] = wr0; wbuf[nxt][tid+256] = wr1;
            sbuf[nxt][tid] = sr0; sbuf[nxt][tid+256] = sr1;
        }
        __syncthreads();
    }

    if (isL){
        int j = j0 + w;
        size_t xb = (size_t)t*8192*SB;
        float gi = red2(acc[0]) + d_Xg[xb + (size_t)(j       )*SB + lane];
        float gf = red2(acc[1]) + d_Xg[xb + (size_t)(j + 2048)*SB + lane];
        float gg = red2(acc[2]) + d_Xg[xb + (size_t)(j + 4096)*SB + lane];
        float go = red2(acc[3]) + d_Xg[xb + (size_t)(j + 6144)*SB + lane];
        int ci = ((j>>2)*SB + lane)*4 + (j&3);
        float cold = d_c[ci];
        float cn = sigf(gf)*cold + sigf(gi)*tanhf(gg);
        d_c[ci] = cn;
        d_h[wp][ci] = sigf(go)*tanhf(cn);
    } else {
        #pragma unroll
        for (int g = 0; g < 4; g++){
            int j = rb + w*4 + g;
            d_gh[(size_t)j*SB + lane] = red2(acc[g]) + gbhh[j];
        }
    }
}

// ---- stepB: gi = c@gWih^T + GRU elementwise. 256 blocks, 24 rows (8 cols x 3 gates) ----
__global__ void __launch_bounds__(256, 3) stepB_kernel(
        const float4* __restrict__ gWih4, const float* __restrict__ gbih, int t){
    __shared__ float4 wbuf[2][384];   // 24 rows x 16 f4
    __shared__ float4 sbuf[2][512];
    int rp = t & 1, wp = rp ^ 1;
    int tid = threadIdx.x, lane = tid & 31, w = tid >> 5;
    int j0 = blockIdx.x * 8;
    const float4* S4 = (const float4*)(d_c);
    int r0 = tid >> 4, kc0 = tid & 15;
    int r1 = r0 + 16;                 // rows 16..23 for tid < 128
    int rowg0 = (r0>>3)*2048 + j0 + (r0&7);
    int rowg1 = (r1>>3)*2048 + j0 + (r1&7);
    const float4* wg0 = gWih4 + (size_t)rowg0*NKQ + kc0;
    const float4* wg1 = gWih4 + (size_t)rowg1*NKQ + kc0;
    bool has2 = (tid < 128);
    int wOff[3];
    #pragma unroll
    for (int g = 0; g < 3; g++) wOff[g] = (g*8 + w)*16;

    float4 wr0 = wg0[0];
    float4 wr1 = has2 ? wg1[0] : make_float4(0,0,0,0);
    float4 sr0 = S4[tid], sr1 = S4[tid + 256];
    wbuf[0][tid] = wr0; if (has2) wbuf[0][tid+256] = wr1;
    sbuf[0][tid] = sr0; sbuf[0][tid+256] = sr1;
    __syncthreads();

    u64 acc[3] = {0ull,0ull,0ull};
    #pragma unroll 1
    for (int ck = 0; ck < NCH; ck++){
        int cur = ck & 1;
        if (ck < NCH-1){
            wr0 = wg0[(ck+1)*CHQ];
            if (has2) wr1 = wg1[(ck+1)*CHQ];
            sr0 = S4[(ck+1)*512 + tid]; sr1 = S4[(ck+1)*512 + tid + 256];
        }
        #pragma unroll
        for (int kq = 0; kq < CHQ; kq++){
            float4 sv = sbuf[cur][kq*32 + lane];
            u64 slo = pk2(sv.x, sv.y), shi = pk2(sv.z, sv.w);
            #pragma unroll
            for (int g = 0; g < 3; g++){
                float4 wv = wbuf[cur][wOff[g] + kq];
                acc[g] = ffma2(pk2(wv.x,wv.y), slo, acc[g]);
                acc[g] = ffma2(pk2(wv.z,wv.w), shi, acc[g]);
            }
        }
        if (ck < NCH-1){
            int nxt = cur ^ 1;
            wbuf[nxt][tid] = wr0; if (has2) wbuf[nxt][tid+256] = wr1;
            sbuf[nxt][tid] = sr0; sbuf[nxt][tid+256] = sr1;
        }
        __syncthreads();
    }

    int j = j0 + w;
    float r_ = sigf(red2(acc[0]) + gbih[j       ] + d_gh[(size_t)(j       )*SB + lane]);
    float z_ = sigf(red2(acc[1]) + gbih[j + 2048] + d_gh[(size_t)(j + 2048)*SB + lane]);
    float n_ = tanhf(red2(acc[2]) + gbih[j + 4096] + r_*d_gh[(size_t)(j + 4096)*SB + lane]);
    int ci = ((j>>2)*SB + lane)*4 + (j&3);
    float hgo = d_hg[rp][ci];
    float hg = (1.0f - z_)*n_ + z_*hgo;
    d_hg[wp][ci] = hg;
    d_hgAll[(size_t)t*(SH*SB) + ci] = hg;
}

// ---- final projection: 250 v-groups x 13 t-groups; block = 32 v-rows x 3 timesteps ----
__global__ void __launch_bounds__(256, 2) final_kernel(
        const float4* __restrict__ linW4, const float* __restrict__ linb,
        float* __restrict__ out){
    extern __shared__ float4 smemRaw[];
    float4* wb = smemRaw;            // [2][512]
    float4* sb = smemRaw + 1024;     // [2][3*512]
    int tid = threadIdx.x, lane = tid & 31, w = tid >> 5;
    int vp = blockIdx.x % 250, tg = blockIdx.x / 250;
    int v0 = vp*32, t0 = tg*3;
    int r0 = tid >> 4, kc0 = tid & 15;
    const float4* wg0 = linW4 + (size_t)(v0 + r0)*NKQ + kc0;
    const float4* wg1 = linW4 + (size_t)(v0 + r0 + 16)*NKQ + kc0;
    const float4* S0 = (const float4*)(d_hgAll + (size_t)(t0    )*(SH*SB));
    const float4* S1 = (const float4*)(d_hgAll + (size_t)(t0 + 1)*(SH*SB));
    const float4* S2 = (const float4*)(d_hgAll + (size_t)(t0 + 2)*(SH*SB));

    float4 wr0 = wg0[0], wr1 = wg1[0];
    float4 sa0 = S0[tid], sa1 = S0[tid+256];
    float4 sb0 = S1[tid], sb1 = S1[tid+256];
    float4 sc0 = S2[tid], sc1 = S2[tid+256];
    wb[tid] = wr0; wb[tid+256] = wr1;
    sb[tid] = sa0; sb[tid+256] = sa1;
    sb[512+tid] = sb0; sb[512+tid+256] = sb1;
    sb[1024+tid] = sc0; sb[1024+tid+256] = sc1;
    __syncthreads();

    u64 acc[12];
    #pragma unroll
    for (int i = 0; i < 12; i++) acc[i] = 0ull;

    #pragma unroll 1
    for (int ck = 0; ck < NCH; ck++){
        int cur = ck & 1;
        float4* wc = wb + cur*512;
        float4* sc = sb + cur*1536;
        if (ck < NCH-1){
            wr0 = wg0[(ck+1)*CHQ]; wr1 = wg1[(ck+1)*CHQ];
            sa0 = S0[(ck+1)*512 + tid]; sa1 = S0[(ck+1)*512 + tid + 256];
            sb0 = S1[(ck+1)*512 + tid]; sb1 = S1[(ck+1)*512 + tid + 256];
            sc0 = S2[(ck+1)*512 + tid]; sc1 = S2[(ck+1)*512 + tid + 256];
        }
        #pragma unroll
        for (int kq = 0; kq < CHQ; kq++){
            float4 v0s = sc[          kq*32 + lane];
            float4 v1s = sc[ 512 +    kq*32 + lane];
            float4 v2s = sc[1024 +    kq*32 + lane];
            u64 l0 = pk2(v0s.x, v0s.y), m0 = pk2(v0s.z, v0s.w);
            u64 l1 = pk2(v1s.x, v1s.y), m1 = pk2(v1s.z, v1s.w);
            u64 l2 = pk2(v2s.x, v2s.y), m2 = pk2(v2s.z, v2s.w);
            #pragma unroll
            for (int g = 0; g < 4; g++){
                float4 wv = wc[(w*4 + g)*16 + kq];
                u64 wl = pk2(wv.x, wv.y), wh = pk2(wv.z, wv.w);
                acc[0*4+g] = ffma2(wl, l0, acc[0*4+g]); acc[0*4+g] = ffma2(wh, m0, acc[0*4+g]);
                acc[1*4+g] = ffma2(wl, l1, acc[1*4+g]); acc[1*4+g] = ffma2(wh, m1, acc[1*4+g]);
                acc[2*4+g] = ffma2(wl, l2, acc[2*4+g]); acc[2*4+g] = ffma2(wh, m2, acc[2*4+g]);
            }
        }
        if (ck < NCH-1){
            int nxt = cur ^ 1;
            float4* wn = wb + nxt*512;
            float4* sn = sb + nxt*1536;
            wn[tid] = wr0; wn[tid+256] = wr1;
            sn[tid] = sa0; sn[tid+256] = sa1;
            sn[512+tid] = sb0; sn[512+tid+256] = sb1;
            sn[1024+tid] = sc0; sn[1024+tid+256] = sc1;
        }
        __syncthreads();
    }

    int v = v0 + w*4;
    float4 lb = *(const float4*)(linb + v);
    #pragma unroll
    for (int tt = 0; tt < 3; tt++){
        float4 ov;
        ov.x = red2(acc[tt*4+0]) + lb.x;
        ov.y = red2(acc[tt*4+1]) + lb.y;
        ov.z = red2(acc[tt*4+2]) + lb.z;
        ov.w = red2(acc[tt*4+3]) + lb.w;
        *(float4*)(out + (size_t)lane*(ST*SV) + (size_t)(t0+tt)*SV + v) = ov;
    }
}

extern "C" void kernel_launch(void* const* d_in, const int* in_sizes, int n_in,
                              void* d_out, int out_size){
    const float* features = (const float*)d_in[0];
    const int*   captions = (const int*)  d_in[1];
    const float* emb      = (const float*)d_in[2];
    const float* lWih     = (const float*)d_in[3];
    const float* lbih     = (const float*)d_in[4];
    const float* lWhh     = (const float*)d_in[5];
    const float* lbhh     = (const float*)d_in[6];
    const float* gWih     = (const float*)d_in[7];
    const float* gbih     = (const float*)d_in[8];
    const float* gWhh     = (const float*)d_in[9];
    const float* gbhh     = (const float*)d_in[10];
    const float* linW     = (const float*)d_in[11];
    const float* linb     = (const float*)d_in[12];
    float* out = (float*)d_out;

    cudaFuncSetAttribute(final_kernel, cudaFuncAttributeMaxDynamicSharedMemorySize, 65536);

    setup_kernel<<<256, 256>>>(features);
    xg_kernel<<<dim3(ST, 8), 256>>>(captions, emb, lWih, lbih, lbhh);
    for (int t = 0; t < ST; t++){
        stepA_kernel<<<448, 256>>>((const float4*)lWhh, (const float4*)gWhh, gbhh, t);
        stepB_kernel<<<256, 256>>>((const float4*)gWih, gbih, t);
    }
    final_kernel<<<3250, 256, 65536>>>((const float4*)linW, linb, out);
}